// round 12
// baseline (speedup 1.0000x reference)
#include <cuda_runtime.h>
#include <cuda_fp16.h>
#include <cstdint>

// SkeletalEncBlock: pool-folded weights + implicit-conv GEMM, fp16 m16n8k16.
// R12: m32 warps (2 m16 frags) with TT=256 — each B (W) LDS.128 feeds 4 MMAs,
// halving smem B traffic per unit work. 2 CTAs/SM.

#define J     24
#define CIN   32
#define COUT  32
#define KS    15
#define PADT  7
#define BATCH 32
#define TDIM  4096
#define NG    12
#define TT    256
#define WIN   (TT + KS - 1)   // 270
#define NCHK  8               // k16-chunks (128 icl)
#define CHUNKB (WIN * 32)     // 8640 B per chunk (32B per t-row)
#define XELEMS (128 * WIN)    // 34560 = 135 * 256 exactly

#define SM_X     0
#define X_BYTES  (NCHK * CHUNKB)       // 69120
#define SM_B     X_BYTES
#define BUF_B    16384                 // one round: 2 taps x 8KB
#define SM_TOTAL (SM_B + 2 * BUF_B)    // 101888 -> 2 CTAs/SM

// W pack (halves): [g][tap][chunk(8)][nfp(2)][lane(32)][8 halves]
//   j in 0..7: nf = nfp*2 + (j>>2), jj = j&3,
//   oc = nf*8 + (lane>>2), k = (lane&3)*2 + (jj&1) + (jj>>1)*8, icl = chunk*16+k
__device__ __half g_wpack[NG * KS * 4096];
__device__ float  g_biasp[NG * 32];

__device__ __forceinline__ unsigned smem_u32(const void* p) {
    unsigned a;
    asm("{ .reg .u64 t; cvta.to.shared.u64 t, %1; cvt.u32.u64 %0, t; }"
        : "=r"(a) : "l"(p));
    return a;
}
#define CP16(dst, src) \
    asm volatile("cp.async.ca.shared.global [%0], [%1], 16;" \
                 :: "r"(dst), "l"(src))
#define CP_COMMIT() asm volatile("cp.async.commit_group;")
#define CP_WAIT1()  asm volatile("cp.async.wait_group 1;")
#define CP_WAIT0()  asm volatile("cp.async.wait_group 0;")

// ---------------- prep: pool + mask + pack fp16 W ----------------
__global__ void prep_kernel(const float* __restrict__ w,
                            const float* __restrict__ bias) {
    int idx = blockIdx.x * blockDim.x + threadIdx.x;
    const int total = NG * KS * 4096;
    if (idx < total) {
        int j     = idx & 7;
        int lane  = (idx >> 3) & 31;
        int nfp   = (idx >> 8) & 1;
        int chunk = (idx >> 9) & 7;
        int gt    = idx >> 12;
        int tap   = gt % KS, g = gt / KS;
        int nf = nfp * 2 + (j >> 2);
        int jj = j & 3;
        int oc = nf * 8 + (lane >> 2);
        int k  = (lane & 3) * 2 + (jj & 1) + ((jj >> 1) << 3);
        int icl = chunk * 16 + k;
        int ji  = 2 * g - 1 + (icl >> 5);
        int cin = icl & 31;
        float v = 0.f;
        if (ji >= 0 && ji < J) {
            #pragma unroll
            for (int p = 0; p < 2; p++) {
                int jo = 2 * g + p;
                if (ji >= jo - 1 && ji <= jo + 1)
                    v += w[((long)(jo * COUT + oc) * (J * CIN)
                            + ji * CIN + cin) * KS + tap];
            }
        }
        g_wpack[idx] = __float2half_rn(0.5f * v);
    }
    if (idx < NG * 32) {
        int g = idx >> 5, oc = idx & 31;
        g_biasp[idx] = 0.5f * (bias[(2 * g) * COUT + oc]
                             + bias[(2 * g + 1) * COUT + oc]);
    }
}

// ---------------- main kernel ----------------
extern __shared__ char smem[];

__device__ __forceinline__ void stage_w(int r, int g, int tid, unsigned sb) {
    int half = tid >> 7;           // which of 2 taps this thread stages
    int wi   = tid & 127;          // 128 threads x 64B = 8KB per tap
    int tap  = 2 * r + half;
    if (tap > 14) tap = 14;        // clamped duplicate, never consumed
    const char* src = (const char*)g_wpack
        + ((long)(g * KS + tap) * 4096) * 2 + wi * 64;
    unsigned dst = sb + SM_B + (r & 1) * BUF_B + half * 8192 + (unsigned)wi * 64;
    CP16(dst, src);
    CP16(dst + 16, src + 16);
    CP16(dst + 32, src + 32);
    CP16(dst + 48, src + 48);
}

__global__ __launch_bounds__(256, 2)
void conv_kernel(const float* __restrict__ x, float* __restrict__ out) {
    const int tile = blockIdx.x;   // 16 t-windows of 256
    const int g    = blockIdx.y;
    const int bb   = blockIdx.z;
    const int tid  = threadIdx.x;
    const int t0   = tile * TT;
    const unsigned sb = smem_u32(smem);
    const int wid = tid >> 5, lane = tid & 31;

    // round-0 W staging first: hides under the X fill
    stage_w(0, g, tid, sb);
    CP_COMMIT();

    // ---- X fill: [chunk(8)][t(WIN)][16 perm halves] ----
    // perm for icl-in-chunk i: q=i>>3, w=i&7 -> pos = (w>>1)*4 + q*2 + (w&1)
    {
        const long xbase = (long)bb * (J * CIN) * TDIM;
        #pragma unroll 1
        for (int o = 0; o < XELEMS / 256; o++) {
            int idx = o * 256 + tid;
            int icl = idx / WIN, tw = idx - icl * WIN;
            int t = t0 - PADT + tw;
            int ji = 2 * g - 1 + (icl >> 5), cin = icl & 31;
            float v = 0.f;
            if (ji >= 0 && ji < J && t >= 0 && t < TDIM)
                v = __ldg(x + xbase + (long)(ji * CIN + cin) * TDIM + t);
            int chunk = icl >> 4, i = icl & 15;
            int q = i >> 3, wv = i & 7;
            int pos = ((wv >> 1) << 2) + (q << 1) + (wv & 1);
            *reinterpret_cast<__half*>(smem + chunk * CHUNKB + tw * 32 + pos * 2)
                = __float2half_rn(v);
        }
    }

    float acc[2][4][4];
    #pragma unroll
    for (int mf = 0; mf < 2; mf++)
        #pragma unroll
        for (int nf = 0; nf < 4; nf++)
            #pragma unroll
            for (int i2 = 0; i2 < 4; i2++) acc[mf][nf][i2] = 0.f;

    // A base: warp wid owns t rows [wid*32, wid*32+32); row = lane>>2, kq = lane&3
    const unsigned arow = sb + ((unsigned)(wid * 32 + (lane >> 2))) * 32
                        + ((lane & 3) << 3);

    for (int r = 0; r < 8; r++) {
        if (r < 7) { stage_w(r + 1, g, tid, sb); CP_COMMIT(); CP_WAIT1(); }
        else CP_WAIT0();
        __syncthreads();

        #pragma unroll
        for (int tt = 0; tt < 2; tt++) {
            const int tap = 2 * r + tt;
            if (tap > 14) break;
            const unsigned ab = arow + tap * 32;
            const unsigned bbase = sb + SM_B + (r & 1) * BUF_B + tt * 8192
                                 + (unsigned)lane * 16;
            #pragma unroll
            for (int c = 0; c < NCHK; c++) {
                unsigned a[2][4];
                #pragma unroll
                for (int mf = 0; mf < 2; mf++) {
                    unsigned ad = ab + c * CHUNKB + mf * 512;
                    asm volatile("ld.shared.v2.b32 {%0,%1}, [%2];"
                        : "=r"(a[mf][0]), "=r"(a[mf][2]) : "r"(ad));
                    asm volatile("ld.shared.v2.b32 {%0,%1}, [%2];"
                        : "=r"(a[mf][1]), "=r"(a[mf][3]) : "r"(ad + 256));
                }
                #pragma unroll
                for (int nfp = 0; nfp < 2; nfp++) {
                    unsigned b0, b1, b2, b3;
                    asm volatile("ld.shared.v4.b32 {%0,%1,%2,%3}, [%4];"
                        : "=r"(b0), "=r"(b1), "=r"(b2), "=r"(b3)
                        : "r"(bbase + c * 1024 + nfp * 512));
                    #pragma unroll
                    for (int mf = 0; mf < 2; mf++) {
                        asm volatile(
                            "mma.sync.aligned.m16n8k16.row.col.f32.f16.f16.f32 "
                            "{%0,%1,%2,%3}, {%4,%5,%6,%7}, {%8,%9}, {%0,%1,%2,%3};"
                            : "+f"(acc[mf][nfp * 2][0]), "+f"(acc[mf][nfp * 2][1]),
                              "+f"(acc[mf][nfp * 2][2]), "+f"(acc[mf][nfp * 2][3])
                            : "r"(a[mf][0]), "r"(a[mf][1]), "r"(a[mf][2]), "r"(a[mf][3]),
                              "r"(b0), "r"(b1));
                        asm volatile(
                            "mma.sync.aligned.m16n8k16.row.col.f32.f16.f16.f32 "
                            "{%0,%1,%2,%3}, {%4,%5,%6,%7}, {%8,%9}, {%0,%1,%2,%3};"
                            : "+f"(acc[mf][nfp * 2 + 1][0]), "+f"(acc[mf][nfp * 2 + 1][1]),
                              "+f"(acc[mf][nfp * 2 + 1][2]), "+f"(acc[mf][nfp * 2 + 1][3])
                            : "r"(a[mf][0]), "r"(a[mf][1]), "r"(a[mf][2]), "r"(a[mf][3]),
                              "r"(b2), "r"(b3));
                    }
                }
            }
        }
        __syncthreads();
    }

    // ---- epilogue: bias + LeakyReLU + store (each warp owns 32t x 32oc) ----
    {
        const int oc0 = 2 * (lane & 3);
        const long obase = ((long)bb * (NG * COUT) + g * COUT) * TDIM;
        #pragma unroll
        for (int mf = 0; mf < 2; mf++) {
            const int t_ = t0 + wid * 32 + mf * 16 + (lane >> 2);
            #pragma unroll
            for (int nf = 0; nf < 4; nf++) {
                const int oc = nf * 8 + oc0;
                float bi0 = g_biasp[g * 32 + oc];
                float bi1 = g_biasp[g * 32 + oc + 1];
                float v0 = acc[mf][nf][0] + bi0;
                float v1 = acc[mf][nf][1] + bi1;
                float v2 = acc[mf][nf][2] + bi0;
                float v3 = acc[mf][nf][3] + bi1;
                v0 = v0 >= 0.f ? v0 : 0.2f * v0;
                v1 = v1 >= 0.f ? v1 : 0.2f * v1;
                v2 = v2 >= 0.f ? v2 : 0.2f * v2;
                v3 = v3 >= 0.f ? v3 : 0.2f * v3;
                out[obase + (long)oc * TDIM + t_]           = v0;
                out[obase + (long)(oc + 1) * TDIM + t_]     = v1;
                out[obase + (long)oc * TDIM + t_ + 8]       = v2;
                out[obase + (long)(oc + 1) * TDIM + t_ + 8] = v3;
            }
        }
    }
}

extern "C" void kernel_launch(void* const* d_in, const int* in_sizes, int n_in,
                              void* d_out, int out_size) {
    const float* x      = (const float*)d_in[0];
    const float* weight = (const float*)d_in[1];
    const float* bias   = (const float*)d_in[2];
    // d_in[3] mask / d_in[4] pool_pairs: deterministic topology, folded in prep.
    float* out = (float*)d_out;

    const int total = NG * KS * 4096;
    prep_kernel<<<(total + 255) / 256, 256>>>(weight, bias);

    cudaFuncSetAttribute(conv_kernel,
                         cudaFuncAttributeMaxDynamicSharedMemorySize, SM_TOTAL);
    dim3 grid(TDIM / TT, NG, BATCH);
    conv_kernel<<<grid, 256, SM_TOTAL>>>(x, out);
}

// round 13
// speedup vs baseline: 1.2126x; 1.2126x over previous
#include <cuda_runtime.h>
#include <cuda_fp16.h>
#include <cstdint>

// SkeletalEncBlock: pool-folded weights + implicit-conv GEMM, fp16 m16n8k16.
// R13: TT=128 with 4 m-warps (m=32) x 2 tap-groups -> 2 wf/MMA at 3 CTAs/SM
// (R12's traffic efficiency at R11's occupancy). One-shot smem reduction.

#define J     24
#define CIN   32
#define COUT  32
#define KS    15
#define PADT  7
#define BATCH 32
#define TDIM  4096
#define NG    12
#define TT    128
#define WIN   (TT + KS - 1)   // 142
#define PITCH 144
#define NCHK  8               // k16-chunks (128 icl)
#define CHUNKB (PITCH * 32)   // 4608 B per chunk (32B per t-row)
#define XELEMS (128 * WIN)    // 18176 = 71 * 256 exactly

#define SM_X     0
#define X_BYTES  (NCHK * CHUNKB)       // 36864
#define SM_B     X_BYTES
#define BUF_B    16384                 // one round: 2 taps (one per group) x 8KB
#define SM_TOTAL (SM_B + 2 * BUF_B)    // 69632 -> 3 CTAs/SM

// W pack (halves): [g][tap][chunk(8)][nfp(2)][lane(32)][8 halves]
//   j in 0..7: nf = nfp*2 + (j>>2), jj = j&3,
//   oc = nf*8 + (lane>>2), k = (lane&3)*2 + (jj&1) + (jj>>1)*8, icl = chunk*16+k
__device__ __half g_wpack[NG * KS * 4096];
__device__ float  g_biasp[NG * 32];

__device__ __forceinline__ unsigned smem_u32(const void* p) {
    unsigned a;
    asm("{ .reg .u64 t; cvta.to.shared.u64 t, %1; cvt.u32.u64 %0, t; }"
        : "=r"(a) : "l"(p));
    return a;
}
#define CP16(dst, src) \
    asm volatile("cp.async.ca.shared.global [%0], [%1], 16;" \
                 :: "r"(dst), "l"(src))
#define CP_COMMIT() asm volatile("cp.async.commit_group;")
#define CP_WAIT1()  asm volatile("cp.async.wait_group 1;")
#define CP_WAIT0()  asm volatile("cp.async.wait_group 0;")

// ---------------- prep: pool + mask + pack fp16 W ----------------
__global__ void prep_kernel(const float* __restrict__ w,
                            const float* __restrict__ bias) {
    int idx = blockIdx.x * blockDim.x + threadIdx.x;
    const int total = NG * KS * 4096;
    if (idx < total) {
        int j     = idx & 7;
        int lane  = (idx >> 3) & 31;
        int nfp   = (idx >> 8) & 1;
        int chunk = (idx >> 9) & 7;
        int gt    = idx >> 12;
        int tap   = gt % KS, g = gt / KS;
        int nf = nfp * 2 + (j >> 2);
        int jj = j & 3;
        int oc = nf * 8 + (lane >> 2);
        int k  = (lane & 3) * 2 + (jj & 1) + ((jj >> 1) << 3);
        int icl = chunk * 16 + k;
        int ji  = 2 * g - 1 + (icl >> 5);
        int cin = icl & 31;
        float v = 0.f;
        if (ji >= 0 && ji < J) {
            #pragma unroll
            for (int p = 0; p < 2; p++) {
                int jo = 2 * g + p;
                if (ji >= jo - 1 && ji <= jo + 1)
                    v += w[((long)(jo * COUT + oc) * (J * CIN)
                            + ji * CIN + cin) * KS + tap];
            }
        }
        g_wpack[idx] = __float2half_rn(0.5f * v);
    }
    if (idx < NG * 32) {
        int g = idx >> 5, oc = idx & 31;
        g_biasp[idx] = 0.5f * (bias[(2 * g) * COUT + oc]
                             + bias[(2 * g + 1) * COUT + oc]);
    }
}

// ---------------- main kernel ----------------
extern __shared__ char smem[];

__device__ __forceinline__ void stage_w(int r, int g, int tid, unsigned sb) {
    int half = tid >> 7;           // 0: tap r (group 0), 1: tap 8+r (group 1)
    int wi   = tid & 127;          // 128 threads x 64B = 8KB per tap
    int tap  = r + half * 8;
    if (tap > 14) tap = 14;        // clamped duplicate, never consumed
    const char* src = (const char*)g_wpack
        + ((long)(g * KS + tap) * 4096) * 2 + wi * 64;
    unsigned dst = sb + SM_B + (r & 1) * BUF_B + half * 8192 + (unsigned)wi * 64;
    CP16(dst, src);
    CP16(dst + 16, src + 16);
    CP16(dst + 32, src + 32);
    CP16(dst + 48, src + 48);
}

__global__ __launch_bounds__(256, 3)
void conv_kernel(const float* __restrict__ x, float* __restrict__ out) {
    const int tile = blockIdx.x;
    const int g    = blockIdx.y;
    const int bb   = blockIdx.z;
    const int tid  = threadIdx.x;
    const int t0   = tile * TT;
    const unsigned sb = smem_u32(smem);
    const int wid = tid >> 5, lane = tid & 31;
    const int tg = wid >> 2;       // tap group: 0 -> taps 0..7, 1 -> taps 8..14
    const int mw = wid & 3;        // m-warp: rows [mw*32, mw*32+32)

    // round-0 W staging first: hides under the X fill
    stage_w(0, g, tid, sb);
    CP_COMMIT();

    // ---- X fill: [chunk(8)][t(PITCH)][16 perm halves] ----
    // perm for icl-in-chunk i: q=i>>3, w=i&7 -> pos = (w>>1)*4 + q*2 + (w&1)
    {
        const long xbase = (long)bb * (J * CIN) * TDIM;
        #pragma unroll 1
        for (int o = 0; o < XELEMS / 256; o++) {
            int idx = o * 256 + tid;
            int icl = idx / WIN, tw = idx - icl * WIN;
            int t = t0 - PADT + tw;
            int ji = 2 * g - 1 + (icl >> 5), cin = icl & 31;
            float v = 0.f;
            if (ji >= 0 && ji < J && t >= 0 && t < TDIM)
                v = __ldg(x + xbase + (long)(ji * CIN + cin) * TDIM + t);
            int chunk = icl >> 4, i = icl & 15;
            int q = i >> 3, wv = i & 7;
            int pos = ((wv >> 1) << 2) + (q << 1) + (wv & 1);
            *reinterpret_cast<__half*>(smem + chunk * CHUNKB + tw * 32 + pos * 2)
                = __float2half_rn(v);
        }
    }

    float acc[2][4][4];
    #pragma unroll
    for (int mf = 0; mf < 2; mf++)
        #pragma unroll
        for (int nf = 0; nf < 4; nf++)
            #pragma unroll
            for (int i2 = 0; i2 < 4; i2++) acc[mf][nf][i2] = 0.f;

    // A base: warp covers t rows [mw*32, mw*32+32); row = lane>>2, kq = lane&3
    const unsigned arow = sb + ((unsigned)(mw * 32 + (lane >> 2))) * 32
                        + ((lane & 3) << 3);

    for (int r = 0; r < 8; r++) {
        if (r < 7) { stage_w(r + 1, g, tid, sb); CP_COMMIT(); CP_WAIT1(); }
        else CP_WAIT0();
        __syncthreads();

        const int tap = tg * 8 + r;
        if (tap <= 14) {
            const unsigned ab = arow + tap * 32;
            const unsigned bbase = sb + SM_B + (r & 1) * BUF_B + tg * 8192
                                 + (unsigned)lane * 16;
            #pragma unroll
            for (int c = 0; c < NCHK; c++) {
                unsigned a[2][4];
                #pragma unroll
                for (int mf = 0; mf < 2; mf++) {
                    unsigned ad = ab + c * CHUNKB + mf * 512;
                    asm volatile("ld.shared.v2.b32 {%0,%1}, [%2];"
                        : "=r"(a[mf][0]), "=r"(a[mf][2]) : "r"(ad));
                    asm volatile("ld.shared.v2.b32 {%0,%1}, [%2];"
                        : "=r"(a[mf][1]), "=r"(a[mf][3]) : "r"(ad + 256));
                }
                #pragma unroll
                for (int nfp = 0; nfp < 2; nfp++) {
                    unsigned b0, b1, b2, b3;
                    asm volatile("ld.shared.v4.b32 {%0,%1,%2,%3}, [%4];"
                        : "=r"(b0), "=r"(b1), "=r"(b2), "=r"(b3)
                        : "r"(bbase + c * 1024 + nfp * 512));
                    #pragma unroll
                    for (int mf = 0; mf < 2; mf++) {
                        asm volatile(
                            "mma.sync.aligned.m16n8k16.row.col.f32.f16.f16.f32 "
                            "{%0,%1,%2,%3}, {%4,%5,%6,%7}, {%8,%9}, {%0,%1,%2,%3};"
                            : "+f"(acc[mf][nfp * 2][0]), "+f"(acc[mf][nfp * 2][1]),
                              "+f"(acc[mf][nfp * 2][2]), "+f"(acc[mf][nfp * 2][3])
                            : "r"(a[mf][0]), "r"(a[mf][1]), "r"(a[mf][2]), "r"(a[mf][3]),
                              "r"(b0), "r"(b1));
                        asm volatile(
                            "mma.sync.aligned.m16n8k16.row.col.f32.f16.f16.f32 "
                            "{%0,%1,%2,%3}, {%4,%5,%6,%7}, {%8,%9}, {%0,%1,%2,%3};"
                            : "+f"(acc[mf][nfp * 2 + 1][0]), "+f"(acc[mf][nfp * 2 + 1][1]),
                              "+f"(acc[mf][nfp * 2 + 1][2]), "+f"(acc[mf][nfp * 2 + 1][3])
                            : "r"(a[mf][0]), "r"(a[mf][1]), "r"(a[mf][2]), "r"(a[mf][3]),
                              "r"(b2), "r"(b3));
                    }
                }
            }
        }
        __syncthreads();
    }

    // ---- reduce tap-group 1 into group 0 (single dump + add via smem) ----
    // layout: mw*4096 + (mf*4+nf)*512 + lane*16 (float4, conflict-free)
    float4* red = reinterpret_cast<float4*>(smem + SM_B);
    if (tg == 1) {
        #pragma unroll
        for (int mf = 0; mf < 2; mf++)
            #pragma unroll
            for (int nf = 0; nf < 4; nf++)
                red[mw * 256 + (mf * 4 + nf) * 32 + lane] =
                    make_float4(acc[mf][nf][0], acc[mf][nf][1],
                                acc[mf][nf][2], acc[mf][nf][3]);
    }
    __syncthreads();
    if (tg == 0) {
        #pragma unroll
        for (int mf = 0; mf < 2; mf++)
            #pragma unroll
            for (int nf = 0; nf < 4; nf++) {
                float4 v = red[mw * 256 + (mf * 4 + nf) * 32 + lane];
                acc[mf][nf][0] += v.x; acc[mf][nf][1] += v.y;
                acc[mf][nf][2] += v.z; acc[mf][nf][3] += v.w;
            }
        // ---- epilogue: bias + LeakyReLU + store (warp owns 32t x 32oc) ----
        const int oc0 = 2 * (lane & 3);
        const long obase = ((long)bb * (NG * COUT) + g * COUT) * TDIM;
        #pragma unroll
        for (int mf = 0; mf < 2; mf++) {
            const int t_ = t0 + mw * 32 + mf * 16 + (lane >> 2);
            #pragma unroll
            for (int nf = 0; nf < 4; nf++) {
                const int oc = nf * 8 + oc0;
                float bi0 = g_biasp[g * 32 + oc];
                float bi1 = g_biasp[g * 32 + oc + 1];
                float v0 = acc[mf][nf][0] + bi0;
                float v1 = acc[mf][nf][1] + bi1;
                float v2 = acc[mf][nf][2] + bi0;
                float v3 = acc[mf][nf][3] + bi1;
                v0 = v0 >= 0.f ? v0 : 0.2f * v0;
                v1 = v1 >= 0.f ? v1 : 0.2f * v1;
                v2 = v2 >= 0.f ? v2 : 0.2f * v2;
                v3 = v3 >= 0.f ? v3 : 0.2f * v3;
                out[obase + (long)oc * TDIM + t_]           = v0;
                out[obase + (long)(oc + 1) * TDIM + t_]     = v1;
                out[obase + (long)oc * TDIM + t_ + 8]       = v2;
                out[obase + (long)(oc + 1) * TDIM + t_ + 8] = v3;
            }
        }
    }
}

extern "C" void kernel_launch(void* const* d_in, const int* in_sizes, int n_in,
                              void* d_out, int out_size) {
    const float* x      = (const float*)d_in[0];
    const float* weight = (const float*)d_in[1];
    const float* bias   = (const float*)d_in[2];
    // d_in[3] mask / d_in[4] pool_pairs: deterministic topology, folded in prep.
    float* out = (float*)d_out;

    const int total = NG * KS * 4096;
    prep_kernel<<<(total + 255) / 256, 256>>>(weight, bias);

    cudaFuncSetAttribute(conv_kernel,
                         cudaFuncAttributeMaxDynamicSharedMemorySize, SM_TOTAL);
    dim3 grid(TDIM / TT, NG, BATCH);
    conv_kernel<<<grid, 256, SM_TOTAL>>>(x, out);
}

// round 14
// speedup vs baseline: 1.8025x; 1.4865x over previous
#include <cuda_runtime.h>
#include <cuda_fp16.h>
#include <cstdint>

// SkeletalEncBlock: pool-folded weights + implicit-conv GEMM, fp16 m16n8k16.
// R14: X pre-converted/pre-permuted to fp16 panels in global (prep_x), conv
// kernel fills smem with linear cp.async copies (no div, no f2h, no STS
// conflicts). Mainloop = R13 (4 m-warps x 2 tap-groups, 3 CTAs/SM).

#define J     24
#define CIN   32
#define COUT  32
#define KS    15
#define PADT  7
#define BATCH 32
#define TDIM  4096
#define NG    12
#define TT    128
#define WIN   (TT + KS - 1)   // 142
#define NCHK  8               // k16-chunks (128 icl)
#define CHUNKB (WIN * 32)     // 4544 B per chunk (32B per t-row, contiguous)
#define UNITS 50              // 48 real 16-ch units + 1 zero pad each end
#define TPAD  4112            // 4096 + 8 pad each end

#define SM_X     0
#define X_BYTES  (NCHK * CHUNKB)       // 36352
#define SM_B     X_BYTES
#define BUF_B    16384                 // one round: 2 taps (one per group) x 8KB
#define SM_TOTAL (SM_B + 2 * BUF_B)    // 69120 -> 3 CTAs/SM

// pre-permuted fp16 X: [b][unit(50)][trow(4112)][16 halves], pos-permuted
__device__ __half g_xh[(size_t)BATCH * UNITS * TPAD * 16];
// W pack (halves): [g][tap][chunk(8)][nfp(2)][lane(32)][8 halves]
__device__ __half g_wpack[NG * KS * 4096];
__device__ float  g_biasp[NG * 32];

__device__ __forceinline__ unsigned smem_u32(const void* p) {
    unsigned a;
    asm("{ .reg .u64 t; cvta.to.shared.u64 t, %1; cvt.u32.u64 %0, t; }"
        : "=r"(a) : "l"(p));
    return a;
}
#define CP16(dst, src) \
    asm volatile("cp.async.ca.shared.global [%0], [%1], 16;" \
                 :: "r"(dst), "l"(src))
#define CP_COMMIT() asm volatile("cp.async.commit_group;")
#define CP_WAIT1()  asm volatile("cp.async.wait_group 1;")
#define CP_WAIT0()  asm volatile("cp.async.wait_group 0;")

// ---------------- prep 1: pool + mask + pack fp16 W ----------------
__global__ void prep_kernel(const float* __restrict__ w,
                            const float* __restrict__ bias) {
    int idx = blockIdx.x * blockDim.x + threadIdx.x;
    const int total = NG * KS * 4096;
    if (idx < total) {
        int j     = idx & 7;
        int lane  = (idx >> 3) & 31;
        int nfp   = (idx >> 8) & 1;
        int chunk = (idx >> 9) & 7;
        int gt    = idx >> 12;
        int tap   = gt % KS, g = gt / KS;
        int nf = nfp * 2 + (j >> 2);
        int jj = j & 3;
        int oc = nf * 8 + (lane >> 2);
        int k  = (lane & 3) * 2 + (jj & 1) + ((jj >> 1) << 3);
        int icl = chunk * 16 + k;
        int ji  = 2 * g - 1 + (icl >> 5);
        int cin = icl & 31;
        float v = 0.f;
        if (ji >= 0 && ji < J) {
            #pragma unroll
            for (int p = 0; p < 2; p++) {
                int jo = 2 * g + p;
                if (ji >= jo - 1 && ji <= jo + 1)
                    v += w[((long)(jo * COUT + oc) * (J * CIN)
                            + ji * CIN + cin) * KS + tap];
            }
        }
        g_wpack[idx] = __float2half_rn(0.5f * v);
    }
    if (idx < NG * 32) {
        int g = idx >> 5, oc = idx & 31;
        g_biasp[idx] = 0.5f * (bias[(2 * g) * COUT + oc]
                             + bias[(2 * g + 1) * COUT + oc]);
    }
}

// ---------------- prep 2: convert + permute X into g_xh ----------------
// g_xh[b][u][trow][pos(i)] = fp16( x[b][ (u-2 unit) channels ][trow-8] ), 0 at pads.
__global__ void prep_x(const float* __restrict__ x) {
    int trow = blockIdx.x * 256 + threadIdx.x;
    if (trow >= TPAD) return;
    const int u = blockIdx.y, b = blockIdx.z;
    const int t  = trow - 8;
    const int ur = u - 2;
    __align__(16) __half h[16];
    if (ur >= 0 && ur < 48 && t >= 0 && t < TDIM) {
        const int c0 = (ur >> 1) * 32 + (ur & 1) * 16;
        const float* xp = x + ((long)b * (J * CIN) + c0) * TDIM + t;
        #pragma unroll
        for (int i = 0; i < 16; i++) {
            int q = i >> 3, wv = i & 7;
            int pos = ((wv >> 1) << 2) + (q << 1) + (wv & 1);
            h[pos] = __float2half_rn(__ldg(xp + (long)i * TDIM));
        }
    } else {
        #pragma unroll
        for (int i = 0; i < 16; i++) h[i] = __ushort_as_half(0);
    }
    uint4* dst = reinterpret_cast<uint4*>(
        g_xh + ((size_t)(b * UNITS + u) * TPAD + trow) * 16);
    dst[0] = reinterpret_cast<uint4*>(h)[0];
    dst[1] = reinterpret_cast<uint4*>(h)[1];
}

// ---------------- main kernel ----------------
extern __shared__ char smem[];

__device__ __forceinline__ void stage_w(int r, int g, int tid, unsigned sb) {
    int half = tid >> 7;           // 0: tap r (group 0), 1: tap 8+r (group 1)
    int wi   = tid & 127;          // 128 threads x 64B = 8KB per tap
    int tap  = r + half * 8;
    if (tap > 14) tap = 14;        // clamped duplicate, never consumed
    const char* src = (const char*)g_wpack
        + ((long)(g * KS + tap) * 4096) * 2 + wi * 64;
    unsigned dst = sb + SM_B + (r & 1) * BUF_B + half * 8192 + (unsigned)wi * 64;
    CP16(dst, src);
    CP16(dst + 16, src + 16);
    CP16(dst + 32, src + 32);
    CP16(dst + 48, src + 48);
}

__global__ __launch_bounds__(256, 3)
void conv_kernel(float* __restrict__ out) {
    const int tile = blockIdx.x;
    const int g    = blockIdx.y;
    const int bb   = blockIdx.z;
    const int tid  = threadIdx.x;
    const int t0   = tile * TT;
    const unsigned sb = smem_u32(smem);
    const int wid = tid >> 5, lane = tid & 31;
    const int tg = wid >> 2;       // tap group: 0 -> taps 0..7, 1 -> taps 8..14
    const int mw = wid & 3;        // m-warp: rows [mw*32, mw*32+32)

    // W round-0 (group 0 in flight)
    stage_w(0, g, tid, sb);
    CP_COMMIT();

    // ---- X fill: 8 linear 4544B cp.async copies from g_xh (group 1) ----
    {
        const char* srcb = (const char*)g_xh
            + ((size_t)(bb * UNITS + 4 * g) * TPAD + (t0 + 1)) * 32;
        #pragma unroll
        for (int c = 0; c < NCHK; c++) {
            const char* s = srcb + (size_t)c * (TPAD * 32);
            unsigned d = sb + c * CHUNKB;
            #pragma unroll
            for (int i = 0; i < 2; i++) {
                int e = tid + i * 256;
                if (e < CHUNKB / 16) CP16(d + e * 16, s + (long)e * 16);
            }
        }
        CP_COMMIT();
    }

    float acc[2][4][4];
    #pragma unroll
    for (int mf = 0; mf < 2; mf++)
        #pragma unroll
        for (int nf = 0; nf < 4; nf++)
            #pragma unroll
            for (int i2 = 0; i2 < 4; i2++) acc[mf][nf][i2] = 0.f;

    // A base: warp covers t rows [mw*32, mw*32+32); row = lane>>2, kq = lane&3
    const unsigned arow = sb + ((unsigned)(mw * 32 + (lane >> 2))) * 32
                        + ((lane & 3) << 3);

    for (int r = 0; r < 8; r++) {
        if (r < 7) { stage_w(r + 1, g, tid, sb); CP_COMMIT(); CP_WAIT1(); }
        else CP_WAIT0();
        __syncthreads();

        const int tap = tg * 8 + r;
        if (tap <= 14) {
            const unsigned ab = arow + tap * 32;
            const unsigned bbase = sb + SM_B + (r & 1) * BUF_B + tg * 8192
                                 + (unsigned)lane * 16;
            #pragma unroll
            for (int c = 0; c < NCHK; c++) {
                unsigned a[2][4];
                #pragma unroll
                for (int mf = 0; mf < 2; mf++) {
                    unsigned ad = ab + c * CHUNKB + mf * 512;
                    asm volatile("ld.shared.v2.b32 {%0,%1}, [%2];"
                        : "=r"(a[mf][0]), "=r"(a[mf][2]) : "r"(ad));
                    asm volatile("ld.shared.v2.b32 {%0,%1}, [%2];"
                        : "=r"(a[mf][1]), "=r"(a[mf][3]) : "r"(ad + 256));
                }
                #pragma unroll
                for (int nfp = 0; nfp < 2; nfp++) {
                    unsigned b0, b1, b2, b3;
                    asm volatile("ld.shared.v4.b32 {%0,%1,%2,%3}, [%4];"
                        : "=r"(b0), "=r"(b1), "=r"(b2), "=r"(b3)
                        : "r"(bbase + c * 1024 + nfp * 512));
                    #pragma unroll
                    for (int mf = 0; mf < 2; mf++) {
                        asm volatile(
                            "mma.sync.aligned.m16n8k16.row.col.f32.f16.f16.f32 "
                            "{%0,%1,%2,%3}, {%4,%5,%6,%7}, {%8,%9}, {%0,%1,%2,%3};"
                            : "+f"(acc[mf][nfp * 2][0]), "+f"(acc[mf][nfp * 2][1]),
                              "+f"(acc[mf][nfp * 2][2]), "+f"(acc[mf][nfp * 2][3])
                            : "r"(a[mf][0]), "r"(a[mf][1]), "r"(a[mf][2]), "r"(a[mf][3]),
                              "r"(b0), "r"(b1));
                        asm volatile(
                            "mma.sync.aligned.m16n8k16.row.col.f32.f16.f16.f32 "
                            "{%0,%1,%2,%3}, {%4,%5,%6,%7}, {%8,%9}, {%0,%1,%2,%3};"
                            : "+f"(acc[mf][nfp * 2 + 1][0]), "+f"(acc[mf][nfp * 2 + 1][1]),
                              "+f"(acc[mf][nfp * 2 + 1][2]), "+f"(acc[mf][nfp * 2 + 1][3])
                            : "r"(a[mf][0]), "r"(a[mf][1]), "r"(a[mf][2]), "r"(a[mf][3]),
                              "r"(b2), "r"(b3));
                    }
                }
            }
        }
        __syncthreads();
    }

    // ---- reduce tap-group 1 into group 0 (single dump + add via smem) ----
    float4* red = reinterpret_cast<float4*>(smem + SM_B);
    if (tg == 1) {
        #pragma unroll
        for (int mf = 0; mf < 2; mf++)
            #pragma unroll
            for (int nf = 0; nf < 4; nf++)
                red[mw * 256 + (mf * 4 + nf) * 32 + lane] =
                    make_float4(acc[mf][nf][0], acc[mf][nf][1],
                                acc[mf][nf][2], acc[mf][nf][3]);
    }
    __syncthreads();
    if (tg == 0) {
        #pragma unroll
        for (int mf = 0; mf < 2; mf++)
            #pragma unroll
            for (int nf = 0; nf < 4; nf++) {
                float4 v = red[mw * 256 + (mf * 4 + nf) * 32 + lane];
                acc[mf][nf][0] += v.x; acc[mf][nf][1] += v.y;
                acc[mf][nf][2] += v.z; acc[mf][nf][3] += v.w;
            }
        // ---- epilogue: bias + LeakyReLU + store (warp owns 32t x 32oc) ----
        const int oc0 = 2 * (lane & 3);
        const long obase = ((long)bb * (NG * COUT) + g * COUT) * TDIM;
        #pragma unroll
        for (int mf = 0; mf < 2; mf++) {
            const int t_ = t0 + mw * 32 + mf * 16 + (lane >> 2);
            #pragma unroll
            for (int nf = 0; nf < 4; nf++) {
                const int oc = nf * 8 + oc0;
                float bi0 = g_biasp[g * 32 + oc];
                float bi1 = g_biasp[g * 32 + oc + 1];
                float v0 = acc[mf][nf][0] + bi0;
                float v1 = acc[mf][nf][1] + bi1;
                float v2 = acc[mf][nf][2] + bi0;
                float v3 = acc[mf][nf][3] + bi1;
                v0 = v0 >= 0.f ? v0 : 0.2f * v0;
                v1 = v1 >= 0.f ? v1 : 0.2f * v1;
                v2 = v2 >= 0.f ? v2 : 0.2f * v2;
                v3 = v3 >= 0.f ? v3 : 0.2f * v3;
                out[obase + (long)oc * TDIM + t_]           = v0;
                out[obase + (long)(oc + 1) * TDIM + t_]     = v1;
                out[obase + (long)oc * TDIM + t_ + 8]       = v2;
                out[obase + (long)(oc + 1) * TDIM + t_ + 8] = v3;
            }
        }
    }
}

extern "C" void kernel_launch(void* const* d_in, const int* in_sizes, int n_in,
                              void* d_out, int out_size) {
    const float* x      = (const float*)d_in[0];
    const float* weight = (const float*)d_in[1];
    const float* bias   = (const float*)d_in[2];
    // d_in[3] mask / d_in[4] pool_pairs: deterministic topology, folded in prep.
    float* out = (float*)d_out;

    const int total = NG * KS * 4096;
    prep_kernel<<<(total + 255) / 256, 256>>>(weight, bias);

    dim3 gx((TPAD + 255) / 256, UNITS, BATCH);
    prep_x<<<gx, 256>>>(x);

    cudaFuncSetAttribute(conv_kernel,
                         cudaFuncAttributeMaxDynamicSharedMemorySize, SM_TOTAL);
    dim3 grid(TDIM / TT, NG, BATCH);
    conv_kernel<<<grid, 256, SM_TOTAL>>>(out);
}

// round 15
// speedup vs baseline: 2.3846x; 1.3229x over previous
#include <cuda_runtime.h>
#include <cuda_fp16.h>
#include <cstdint>

// SkeletalEncBlock: pool-folded weights + implicit-conv GEMM, fp16 m16n8k16.
// R15: W (B operand) loaded global->register with distance-1 prefetch (panels
// are L2/L1 resident), W smem pipeline deleted: 3 block syncs total, smem = X
// only (36.4KB), crossbar carries A traffic only. X via cp.async from
// pre-permuted g_xh (R14).

#define J     24
#define CIN   32
#define COUT  32
#define KS    15
#define PADT  7
#define BATCH 32
#define TDIM  4096
#define NG    12
#define TT    128
#define WIN   (TT + KS - 1)   // 142
#define NCHK  8               // k16-chunks (128 icl)
#define CHUNKB (WIN * 32)     // 4544 B per chunk (32B per t-row, contiguous)
#define UNITS 50              // 48 real 16-ch units + 1 zero pad each end
#define TPAD  4112            // 4096 + 8 pad each end

#define X_BYTES  (NCHK * CHUNKB)       // 36352
#define SM_TOTAL X_BYTES               // reduction overlays X after a barrier

// pre-permuted fp16 X: [b][unit(50)][trow(4112)][16 halves], pos-permuted
__device__ __half g_xh[(size_t)BATCH * UNITS * TPAD * 16];
// W pack (halves): [g][tap][chunk(8)][nfp(2)][lane(32)][8 halves]
__device__ __half g_wpack[NG * KS * 4096];
__device__ float  g_biasp[NG * 32];

__device__ __forceinline__ unsigned smem_u32(const void* p) {
    unsigned a;
    asm("{ .reg .u64 t; cvta.to.shared.u64 t, %1; cvt.u32.u64 %0, t; }"
        : "=r"(a) : "l"(p));
    return a;
}
#define CP16(dst, src) \
    asm volatile("cp.async.ca.shared.global [%0], [%1], 16;" \
                 :: "r"(dst), "l"(src))
#define CP_COMMIT() asm volatile("cp.async.commit_group;")
#define CP_WAIT0()  asm volatile("cp.async.wait_group 0;")

// ---------------- prep 1: pool + mask + pack fp16 W ----------------
__global__ void prep_kernel(const float* __restrict__ w,
                            const float* __restrict__ bias) {
    int idx = blockIdx.x * blockDim.x + threadIdx.x;
    const int total = NG * KS * 4096;
    if (idx < total) {
        int j     = idx & 7;
        int lane  = (idx >> 3) & 31;
        int nfp   = (idx >> 8) & 1;
        int chunk = (idx >> 9) & 7;
        int gt    = idx >> 12;
        int tap   = gt % KS, g = gt / KS;
        int nf = nfp * 2 + (j >> 2);
        int jj = j & 3;
        int oc = nf * 8 + (lane >> 2);
        int k  = (lane & 3) * 2 + (jj & 1) + ((jj >> 1) << 3);
        int icl = chunk * 16 + k;
        int ji  = 2 * g - 1 + (icl >> 5);
        int cin = icl & 31;
        float v = 0.f;
        if (ji >= 0 && ji < J) {
            #pragma unroll
            for (int p = 0; p < 2; p++) {
                int jo = 2 * g + p;
                if (ji >= jo - 1 && ji <= jo + 1)
                    v += w[((long)(jo * COUT + oc) * (J * CIN)
                            + ji * CIN + cin) * KS + tap];
            }
        }
        g_wpack[idx] = __float2half_rn(0.5f * v);
    }
    if (idx < NG * 32) {
        int g = idx >> 5, oc = idx & 31;
        g_biasp[idx] = 0.5f * (bias[(2 * g) * COUT + oc]
                             + bias[(2 * g + 1) * COUT + oc]);
    }
}

// ---------------- prep 2: convert + permute X into g_xh ----------------
__global__ void prep_x(const float* __restrict__ x) {
    int trow = blockIdx.x * 256 + threadIdx.x;
    if (trow >= TPAD) return;
    const int u = blockIdx.y, b = blockIdx.z;
    const int t  = trow - 8;
    const int ur = u - 2;
    __align__(16) __half h[16];
    if (ur >= 0 && ur < 48 && t >= 0 && t < TDIM) {
        const int c0 = (ur >> 1) * 32 + (ur & 1) * 16;
        const float* xp = x + ((long)b * (J * CIN) + c0) * TDIM + t;
        #pragma unroll
        for (int i = 0; i < 16; i++) {
            int q = i >> 3, wv = i & 7;
            int pos = ((wv >> 1) << 2) + (q << 1) + (wv & 1);
            h[pos] = __float2half_rn(__ldg(xp + (long)i * TDIM));
        }
    } else {
        #pragma unroll
        for (int i = 0; i < 16; i++) h[i] = __ushort_as_half(0);
    }
    uint4* dst = reinterpret_cast<uint4*>(
        g_xh + ((size_t)(b * UNITS + u) * TPAD + trow) * 16);
    dst[0] = reinterpret_cast<uint4*>(h)[0];
    dst[1] = reinterpret_cast<uint4*>(h)[1];
}

// ---------------- main kernel ----------------
extern __shared__ char smem[];

__global__ __launch_bounds__(256, 3)
void conv_kernel(float* __restrict__ out) {
    const int tile = blockIdx.x;
    const int g    = blockIdx.y;
    const int bb   = blockIdx.z;
    const int tid  = threadIdx.x;
    const int t0   = tile * TT;
    const unsigned sb = smem_u32(smem);
    const int wid = tid >> 5, lane = tid & 31;
    const int tg = wid >> 2;       // tap group: 0 -> taps 0..7, 1 -> taps 8..14
    const int mw = wid & 3;        // m-warp: rows [mw*32, mw*32+32)

    // ---- X fill: 8 linear 4544B cp.async copies from g_xh ----
    {
        const char* srcb = (const char*)g_xh
            + ((size_t)(bb * UNITS + 4 * g) * TPAD + (t0 + 1)) * 32;
        #pragma unroll
        for (int c = 0; c < NCHK; c++) {
            const char* s = srcb + (size_t)c * (TPAD * 32);
            unsigned d = sb + c * CHUNKB;
            #pragma unroll
            for (int i = 0; i < 2; i++) {
                int e = tid + i * 256;
                if (e < CHUNKB / 16) CP16(d + e * 16, s + (long)e * 16);
            }
        }
        CP_COMMIT();
    }

    float acc[2][4][4];
    #pragma unroll
    for (int mf = 0; mf < 2; mf++)
        #pragma unroll
        for (int nf = 0; nf < 4; nf++)
            #pragma unroll
            for (int i2 = 0; i2 < 4; i2++) acc[mf][nf][i2] = 0.f;

    // A base: warp covers t rows [mw*32, mw*32+32); row = lane>>2, kq = lane&3
    const unsigned arow = sb + ((unsigned)(mw * 32 + (lane >> 2))) * 32
                        + ((lane & 3) << 3);

    // B panels straight from global: [tap][chunk(64 u4)][nfp(32 u4)][lane]
    const uint4* wpanel = reinterpret_cast<const uint4*>(
        g_wpack + (size_t)g * KS * 4096);

    // prefetch first B frags (tap tg*8, chunk 0)
    uint4 bc0, bc1;
    {
        const uint4* p = wpanel + (tg * 8) * 512 + lane;
        bc0 = __ldg(p);
        bc1 = __ldg(p + 32);
    }

    CP_WAIT0();
    __syncthreads();   // X ready (sync #1)

    #pragma unroll 1
    for (int r = 0; r < 8; r++) {
        const int tap = tg * 8 + r;
        if (tap > 14) break;
        const unsigned ab = arow + tap * 32;
        #pragma unroll
        for (int c = 0; c < NCHK; c++) {
            // distance-1 prefetch of next (tap, chunk) B frags
            int nr = (c == 7) ? r + 1 : r;
            int ntap = tg * 8 + nr;
            if (ntap > 14) ntap = 14;
            const uint4* np = wpanel + ntap * 512 + ((c + 1) & 7) * 64 + lane;
            uint4 bn0 = __ldg(np);
            uint4 bn1 = __ldg(np + 32);

            unsigned a[2][4];
            #pragma unroll
            for (int mf = 0; mf < 2; mf++) {
                unsigned ad = ab + c * CHUNKB + mf * 512;
                asm volatile("ld.shared.v2.b32 {%0,%1}, [%2];"
                    : "=r"(a[mf][0]), "=r"(a[mf][2]) : "r"(ad));
                asm volatile("ld.shared.v2.b32 {%0,%1}, [%2];"
                    : "=r"(a[mf][1]), "=r"(a[mf][3]) : "r"(ad + 256));
            }
            #pragma unroll
            for (int mf = 0; mf < 2; mf++) {
                asm volatile(
                    "mma.sync.aligned.m16n8k16.row.col.f32.f16.f16.f32 "
                    "{%0,%1,%2,%3}, {%4,%5,%6,%7}, {%8,%9}, {%0,%1,%2,%3};"
                    : "+f"(acc[mf][0][0]), "+f"(acc[mf][0][1]),
                      "+f"(acc[mf][0][2]), "+f"(acc[mf][0][3])
                    : "r"(a[mf][0]), "r"(a[mf][1]), "r"(a[mf][2]), "r"(a[mf][3]),
                      "r"(bc0.x), "r"(bc0.y));
                asm volatile(
                    "mma.sync.aligned.m16n8k16.row.col.f32.f16.f16.f32 "
                    "{%0,%1,%2,%3}, {%4,%5,%6,%7}, {%8,%9}, {%0,%1,%2,%3};"
                    : "+f"(acc[mf][1][0]), "+f"(acc[mf][1][1]),
                      "+f"(acc[mf][1][2]), "+f"(acc[mf][1][3])
                    : "r"(a[mf][0]), "r"(a[mf][1]), "r"(a[mf][2]), "r"(a[mf][3]),
                      "r"(bc0.z), "r"(bc0.w));
                asm volatile(
                    "mma.sync.aligned.m16n8k16.row.col.f32.f16.f16.f32 "
                    "{%0,%1,%2,%3}, {%4,%5,%6,%7}, {%8,%9}, {%0,%1,%2,%3};"
                    : "+f"(acc[mf][2][0]), "+f"(acc[mf][2][1]),
                      "+f"(acc[mf][2][2]), "+f"(acc[mf][2][3])
                    : "r"(a[mf][0]), "r"(a[mf][1]), "r"(a[mf][2]), "r"(a[mf][3]),
                      "r"(bc1.x), "r"(bc1.y));
                asm volatile(
                    "mma.sync.aligned.m16n8k16.row.col.f32.f16.f16.f32 "
                    "{%0,%1,%2,%3}, {%4,%5,%6,%7}, {%8,%9}, {%0,%1,%2,%3};"
                    : "+f"(acc[mf][3][0]), "+f"(acc[mf][3][1]),
                      "+f"(acc[mf][3][2]), "+f"(acc[mf][3][3])
                    : "r"(a[mf][0]), "r"(a[mf][1]), "r"(a[mf][2]), "r"(a[mf][3]),
                      "r"(bc1.z), "r"(bc1.w));
            }
            bc0 = bn0;
            bc1 = bn1;
        }
    }

    __syncthreads();   // all X reads done; reduction overlays X (sync #2)

    // ---- reduce tap-group 1 into group 0 (single dump + add via smem) ----
    float4* red = reinterpret_cast<float4*>(smem);
    if (tg == 1) {
        #pragma unroll
        for (int mf = 0; mf < 2; mf++)
            #pragma unroll
            for (int nf = 0; nf < 4; nf++)
                red[mw * 256 + (mf * 4 + nf) * 32 + lane] =
                    make_float4(acc[mf][nf][0], acc[mf][nf][1],
                                acc[mf][nf][2], acc[mf][nf][3]);
    }
    __syncthreads();   // sync #3
    if (tg == 0) {
        #pragma unroll
        for (int mf = 0; mf < 2; mf++)
            #pragma unroll
            for (int nf = 0; nf < 4; nf++) {
                float4 v = red[mw * 256 + (mf * 4 + nf) * 32 + lane];
                acc[mf][nf][0] += v.x; acc[mf][nf][1] += v.y;
                acc[mf][nf][2] += v.z; acc[mf][nf][3] += v.w;
            }
        // ---- epilogue: bias + LeakyReLU + store (warp owns 32t x 32oc) ----
        const int oc0 = 2 * (lane & 3);
        const long obase = ((long)bb * (NG * COUT) + g * COUT) * TDIM;
        #pragma unroll
        for (int mf = 0; mf < 2; mf++) {
            const int t_ = t0 + mw * 32 + mf * 16 + (lane >> 2);
            #pragma unroll
            for (int nf = 0; nf < 4; nf++) {
                const int oc = nf * 8 + oc0;
                float bi0 = g_biasp[g * 32 + oc];
                float bi1 = g_biasp[g * 32 + oc + 1];
                float v0 = acc[mf][nf][0] + bi0;
                float v1 = acc[mf][nf][1] + bi1;
                float v2 = acc[mf][nf][2] + bi0;
                float v3 = acc[mf][nf][3] + bi1;
                v0 = v0 >= 0.f ? v0 : 0.2f * v0;
                v1 = v1 >= 0.f ? v1 : 0.2f * v1;
                v2 = v2 >= 0.f ? v2 : 0.2f * v2;
                v3 = v3 >= 0.f ? v3 : 0.2f * v3;
                out[obase + (long)oc * TDIM + t_]           = v0;
                out[obase + (long)(oc + 1) * TDIM + t_]     = v1;
                out[obase + (long)oc * TDIM + t_ + 8]       = v2;
                out[obase + (long)(oc + 1) * TDIM + t_ + 8] = v3;
            }
        }
    }
}

extern "C" void kernel_launch(void* const* d_in, const int* in_sizes, int n_in,
                              void* d_out, int out_size) {
    const float* x      = (const float*)d_in[0];
    const float* weight = (const float*)d_in[1];
    const float* bias   = (const float*)d_in[2];
    // d_in[3] mask / d_in[4] pool_pairs: deterministic topology, folded in prep.
    float* out = (float*)d_out;

    const int total = NG * KS * 4096;
    prep_kernel<<<(total + 255) / 256, 256>>>(weight, bias);

    dim3 gx((TPAD + 255) / 256, UNITS, BATCH);
    prep_x<<<gx, 256>>>(x);

    cudaFuncSetAttribute(conv_kernel,
                         cudaFuncAttributeMaxDynamicSharedMemorySize, SM_TOTAL);
    dim3 grid(TDIM / TT, NG, BATCH);
    conv_kernel<<<grid, 256, SM_TOTAL>>>(out);
}